// round 13
// baseline (speedup 1.0000x reference)
#include <cuda_runtime.h>
#include <cuda_fp16.h>
#include <cstdint>

#define N_ROI 1024
#define FLAT  12544
#define HID   1024
#define EMB   256
#define MTOT  50176

// ---------------- scratch ----------------
__device__ __half g_f[(size_t)N_ROI * 196 * 256];    // NHWC fp16 features
__device__ __half g_cw[9 * 256 * 256];               // conv weights [tap][oc][ic]
__device__ __half g_w1[(size_t)HID * FLAT];          // [col][knew]
__device__ __half g_x[(size_t)N_ROI * FLAT];         // conv out fp16 [roi][o*256+oc]
__device__ float g_hp[4 * 1024 * 1024];              // fc1 split-K partials
__device__ float g_e[(size_t)N_ROI * EMB];
__device__ float g_eT[(size_t)EMB * N_ROI];

// ---------------- helpers ----------------
__device__ __forceinline__ uint32_t smem_u32(const void* p) {
    uint32_t a;
    asm("{ .reg .u64 t; cvta.to.shared.u64 t, %1; cvt.u32.u64 %0, t; }" : "=r"(a) : "l"(p));
    return a;
}
__device__ __forceinline__ void ldsm4(uint32_t& r0, uint32_t& r1, uint32_t& r2, uint32_t& r3,
                                      uint32_t addr) {
    asm volatile("ldmatrix.sync.aligned.m8n8.x4.shared.b16 {%0,%1,%2,%3}, [%4];"
                 : "=r"(r0), "=r"(r1), "=r"(r2), "=r"(r3) : "r"(addr));
}
__device__ __forceinline__ void mma16816(float* d, const uint32_t* a, uint32_t b0, uint32_t b1) {
    asm volatile(
        "mma.sync.aligned.m16n8k16.row.col.f32.f16.f16.f32 "
        "{%0,%1,%2,%3},{%4,%5,%6,%7},{%8,%9},{%0,%1,%2,%3};"
        : "+f"(d[0]), "+f"(d[1]), "+f"(d[2]), "+f"(d[3])
        : "r"(a[0]), "r"(a[1]), "r"(a[2]), "r"(a[3]), "r"(b0), "r"(b1));
}
__device__ __forceinline__ void cpa16(uint32_t dst, const void* src) {
    asm volatile("cp.async.ca.shared.global [%0], [%1], 16;" :: "r"(dst), "l"(src));
}
__device__ __forceinline__ void cpa16z(uint32_t dst, const void* src, uint32_t sz) {
    asm volatile("cp.async.ca.shared.global [%0], [%1], 16, %2;"
                 :: "r"(dst), "l"(src), "r"(sz));
}
__device__ __forceinline__ void cpa_commit() {
    asm volatile("cp.async.commit_group;" ::: "memory");
}
template <int N>
__device__ __forceinline__ void cpa_wait() {
    asm volatile("cp.async.wait_group %0;" :: "n"(N) : "memory");
}

// ---------------- fused prep: nhwc transpose | w1 transpose | conv-w convert --
// blocks [0,1024)            : NHWC fp32->fp16 transpose (64-ch tiles, half2 stores)
// blocks [1024, 1024+12544)  : w1 transpose+permute tile
// blocks [13568, 13568+2304) : conv weight convert
__global__ __launch_bounds__(256) void prep_kernel(const float* __restrict__ feat,
                                                   const float* __restrict__ conv_w,
                                                   const float* __restrict__ w1) {
    extern __shared__ float sm[];            // 64*201 floats for nhwc branch
    int b = blockIdx.x;
    if (b < 1024) {
        int n = b;
        const float* src = feat + (size_t)n * 50176;
        size_t obase = (size_t)n * 50176;
        float (*tile)[201] = (float(*)[201])sm;
        for (int cb = 0; cb < 4; cb++) {     // 64 channels per iteration
            __syncthreads();
            for (int i = threadIdx.x; i < 64 * 196; i += 256) {
                int c = i / 196, p = i % 196;
                tile[c][p] = src[(cb * 64 + c) * 196 + p];
            }
            __syncthreads();
            int c2 = threadIdx.x & 31, p0 = threadIdx.x >> 5;
            for (int p = p0; p < 196; p += 8) {
                __half2 v = __floats2half2_rn(tile[2 * c2][p], tile[2 * c2 + 1][p]);
                *(__half2*)&g_f[obase + (size_t)p * 256 + cb * 64 + 2 * c2] = v;
            }
        }
    } else if (b < 1024 + 12544) {
        int idx = b - 1024;
        int knew0 = (idx % 392) * 32, col0 = (idx / 392) * 32;
        float (*t)[33] = (float(*)[33])sm;
        int tr = threadIdx.x >> 5, tc = threadIdx.x & 31;
#pragma unroll
        for (int i = 0; i < 4; i++) {
            int knew = knew0 + tr + i * 8;
            int oc = knew & 255, o = knew >> 8;
            t[tr + i * 8][tc] = w1[(size_t)(oc * 49 + o) * HID + col0 + tc];
        }
        __syncthreads();
#pragma unroll
        for (int i = 0; i < 4; i++) {
            int crow = tr + i * 8;
            g_w1[(size_t)(col0 + crow) * FLAT + knew0 + tc] = __float2half(t[tc][crow]);
        }
    } else {
        int i = (b - 13568) * 256 + threadIdx.x;
        int t = i >> 16, rem = i & 65535;
        int oc = rem >> 8, ic = rem & 255;
        g_cw[i] = __float2half(conv_w[oc * 2304 + ic * 9 + t]);
    }
}

// ---------------- single-pass fp16 HMMA GEMM, BK=64 chunks, 2-stage ----------
#define ROW_B 144
#define TILE_B (128 * ROW_B)
#define STAGE_B (2 * TILE_B)
template <int MODE>
__global__ __launch_bounds__(256, 2) void gemm_sp(const float* __restrict__ bias) {
    constexpr int TOTAL = MODE ? (3136 / 64) : (2304 / 64);
    extern __shared__ __align__(128) char smem[];
    uint32_t sb = smem_u32(smem);

    int tid = threadIdx.x, lane = tid & 31, wid = tid >> 5;
    int wm = wid >> 1, wn = wid & 1;
    int m0 = blockIdx.y * 128, n0 = blockIdx.x * 128;

    int rL = tid >> 2, sL = tid & 3;
    uint32_t dA0 = rL * ROW_B + sL * 16, dA1 = (rL + 64) * ROW_B + sL * 16;

    int ny0 = 0, oy0 = 0, ox0 = 0, ny1 = 0, oy1 = 0, ox1 = 0;
    size_t a0 = 0, a1 = 0, b0 = 0, b1 = 0;
    if (MODE == 0) {
        int rA0 = m0 + rL, rA1 = rA0 + 64;
        ny0 = rA0 / 49; int o0 = rA0 - ny0 * 49; oy0 = o0 / 7; ox0 = o0 - oy0 * 7;
        ny1 = rA1 / 49; int o1 = rA1 - ny1 * 49; oy1 = o1 / 7; ox1 = o1 - oy1 * 7;
    } else {
        size_t koff = (size_t)blockIdx.z * 3136;
        a0 = (size_t)(m0 + rL) * FLAT + koff + sL * 8;
        a1 = (size_t)(m0 + rL + 64) * FLAT + koff + sL * 8;
        b0 = (size_t)(n0 + rL) * FLAT + koff + sL * 8;
        b1 = (size_t)(n0 + rL + 64) * FLAT + koff + sL * 8;
    }

    float acc[2][8][4];
#pragma unroll
    for (int i = 0; i < 2; i++)
#pragma unroll
        for (int j = 0; j < 8; j++)
#pragma unroll
            for (int q = 0; q < 4; q++) acc[i][j][q] = 0.f;

    auto load_stage = [&](int it, int st) {
        uint32_t base = sb + st * STAGE_B;
        if (MODE == 0) {
            int t = it >> 2;
            int ky = t / 3, kx = t - ky * 3;
            int ic0 = ((it & 3) << 6) + sL * 8;
            int iy0 = 2 * oy0 + ky - 1, ix0 = 2 * ox0 + kx - 1;
            int iy1 = 2 * oy1 + ky - 1, ix1 = 2 * ox1 + kx - 1;
            uint32_t v0 = ((unsigned)iy0 < 14u && (unsigned)ix0 < 14u) ? 16u : 0u;
            uint32_t v1 = ((unsigned)iy1 < 14u && (unsigned)ix1 < 14u) ? 16u : 0u;
            size_t s0 = ((size_t)ny0 * 196 + (v0 ? iy0 * 14 + ix0 : 0)) * 256 + ic0;
            size_t s1 = ((size_t)ny1 * 196 + (v1 ? iy1 * 14 + ix1 : 0)) * 256 + ic0;
            size_t bw0 = (size_t)t * 65536 + (size_t)(n0 + rL) * 256 + ic0;
            cpa16z(base + dA0,              g_f + s0, v0);
            cpa16z(base + dA0 + 64,         g_f + s0 + 32, v0);
            cpa16z(base + dA1,              g_f + s1, v1);
            cpa16z(base + dA1 + 64,         g_f + s1 + 32, v1);
            cpa16(base + TILE_B + dA0,      g_cw + bw0);
            cpa16(base + TILE_B + dA0 + 64, g_cw + bw0 + 32);
            cpa16(base + TILE_B + dA1,      g_cw + bw0 + 64 * 256);
            cpa16(base + TILE_B + dA1 + 64, g_cw + bw0 + 64 * 256 + 32);
        } else {
            size_t ko = (size_t)it * 64;
            cpa16(base + dA0,               g_x + a0 + ko);
            cpa16(base + dA0 + 64,          g_x + a0 + ko + 32);
            cpa16(base + dA1,               g_x + a1 + ko);
            cpa16(base + dA1 + 64,          g_x + a1 + ko + 32);
            cpa16(base + TILE_B + dA0,      g_w1 + b0 + ko);
            cpa16(base + TILE_B + dA0 + 64, g_w1 + b0 + ko + 32);
            cpa16(base + TILE_B + dA1,      g_w1 + b1 + ko);
            cpa16(base + TILE_B + dA1 + 64, g_w1 + b1 + ko + 32);
        }
        cpa_commit();
    };

    uint32_t lmo = (lane & 15) * ROW_B + (lane >> 4) * 16;
    uint32_t aOff = wm * 32 * ROW_B + lmo;
    uint32_t bOff = wn * 64 * ROW_B + lmo;

    load_stage(0, 0);
    for (int it = 0; it < TOTAL; it++) {
        cpa_wait<0>();
        __syncthreads();
        if (it + 1 < TOTAL) load_stage(it + 1, (it + 1) & 1);

        uint32_t base = sb + (it & 1) * STAGE_B;
        uint32_t aA = base + aOff, bB = base + TILE_B + bOff;

#pragma unroll
        for (int ks = 0; ks < 4; ks++) {
            uint32_t a[2][4], b[8][2];
#pragma unroll
            for (int mt = 0; mt < 2; mt++)
                ldsm4(a[mt][0], a[mt][1], a[mt][2], a[mt][3],
                      aA + mt * 16 * ROW_B + ks * 32);
#pragma unroll
            for (int q = 0; q < 4; q++) {
                uint32_t r0, r1, r2, r3;
                ldsm4(r0, r1, r2, r3, bB + q * 16 * ROW_B + ks * 32);
                b[2 * q][0] = r0; b[2 * q][1] = r2;
                b[2 * q + 1][0] = r1; b[2 * q + 1][1] = r3;
            }
#pragma unroll
            for (int mt = 0; mt < 2; mt++)
#pragma unroll
                for (int nt = 0; nt < 8; nt++)
                    mma16816(acc[mt][nt], a[mt], b[nt][0], b[nt][1]);
        }
    }
    __syncthreads();

    int rbase = lane >> 2, cbase = (lane & 3) * 2;
#pragma unroll
    for (int mt = 0; mt < 2; mt++) {
#pragma unroll
        for (int nt = 0; nt < 8; nt++) {
            int n = n0 + wn * 64 + nt * 8 + cbase;
            float b0v = 0.f, b1v = 0.f;
            if (MODE == 0) { b0v = bias[n]; b1v = bias[n + 1]; }
#pragma unroll
            for (int half = 0; half < 2; half++) {
                int m = m0 + wm * 32 + mt * 16 + rbase + half * 8;
                if (MODE == 0) {
                    float v0 = fmaxf(acc[mt][nt][half * 2 + 0] + b0v, 0.f);
                    float v1 = fmaxf(acc[mt][nt][half * 2 + 1] + b1v, 0.f);
                    int roi = m / 49, o = m - roi * 49;
                    size_t dst = (size_t)roi * FLAT + o * 256 + n;
                    *(__half2*)&g_x[dst] = __floats2half2_rn(v0, v1);
                } else {
                    float2 v = make_float2(acc[mt][nt][half * 2 + 0],
                                           acc[mt][nt][half * 2 + 1]);
                    *(float2*)&g_hp[(size_t)blockIdx.z * 1048576 + (size_t)m * HID + n] = v;
                }
            }
        }
    }
}

// ---------------- fc2 (fused reduce+bias+relu) + L2-normalize (R11 loop) -----
__global__ __launch_bounds__(1024) void fc2_kernel(const float* __restrict__ w2,
                                                   const float* __restrict__ b1,
                                                   const float* __restrict__ b2) {
    extern __shared__ float dsm[];
    float* hs   = dsm;                       // [8][1024]
    float* part = dsm + 8192;                // [4][8][256]
    float* sred = dsm + 16384;               // [8][264]
    int n0 = blockIdx.x * 8;
    int tid = threadIdx.x, g = tid >> 8, c = tid & 255;

    for (int i = tid; i < 8192; i += 1024) {
        int r = i >> 10, k = i & 1023;
        size_t off = (size_t)(n0 + r) * HID + k;
        float s = g_hp[off] + g_hp[off + 1048576] + g_hp[off + 2097152] +
                  g_hp[off + 3145728] + b1[k];
        hs[r * 1024 + k] = fmaxf(s, 0.f);
    }
    __syncthreads();

    float acc[8];
#pragma unroll
    for (int r = 0; r < 8; r++) acc[r] = 0.f;
    int k0 = g * 256;
#pragma unroll 4
    for (int kk = 0; kk < 256; kk++) {
        float w = w2[(size_t)(k0 + kk) * 256 + c];
#pragma unroll
        for (int r = 0; r < 8; r++)
            acc[r] += hs[r * 1024 + k0 + kk] * w;
    }
#pragma unroll
    for (int r = 0; r < 8; r++)
        part[(g * 8 + r) * 256 + c] = acc[r];
    __syncthreads();

    float val[2];
#pragma unroll
    for (int h = 0; h < 2; h++) {
        int r = g + h * 4;
        val[h] = part[(0 * 8 + r) * 256 + c] + part[(1 * 8 + r) * 256 + c] +
                 part[(2 * 8 + r) * 256 + c] + part[(3 * 8 + r) * 256 + c] + b2[c];
        sred[r * 264 + c] = val[h] * val[h];
    }
    __syncthreads();
    for (int s = 128; s > 0; s >>= 1) {
        if (c < s) {
            sred[g * 264 + c] += sred[g * 264 + c + s];
            sred[(g + 4) * 264 + c] += sred[(g + 4) * 264 + c + s];
        }
        __syncthreads();
    }
#pragma unroll
    for (int h = 0; h < 2; h++) {
        int r = g + h * 4;
        float v = val[h] / sqrtf(sred[r * 264]);
        g_e[(size_t)(n0 + r) * EMB + c] = v;
        g_eT[(size_t)c * N_ROI + (n0 + r)] = v;
    }
}

// ---------------- pairwise, float4 k (R12) ----------------
#define TI 16
__global__ __launch_bounds__(256) void pair_kernel(const float* __restrict__ wm,
                                                   const float* __restrict__ bm,
                                                   float* __restrict__ out) {
    int i0 = blockIdx.y * TI;
    int j0 = blockIdx.x * 256;
    if (j0 + 255 <= i0) return;

    __shared__ float ei[TI][256];
    __shared__ float wms[256];
    int tid = threadIdx.x;
    wms[tid] = wm[tid];
#pragma unroll
    for (int r = 0; r < TI; r++)
        ei[r][tid] = g_e[(size_t)(i0 + r) * EMB + tid];
    __syncthreads();

    int j = j0 + tid;
    float acc[TI];
#pragma unroll
    for (int r = 0; r < TI; r++) acc[r] = 0.f;

#pragma unroll 2
    for (int k = 0; k < 256; k += 4) {
        float4 w4 = *(const float4*)&wms[k];
        float vj0 = g_eT[(size_t)k * N_ROI + j];
        float vj1 = g_eT[(size_t)(k + 1) * N_ROI + j];
        float vj2 = g_eT[(size_t)(k + 2) * N_ROI + j];
        float vj3 = g_eT[(size_t)(k + 3) * N_ROI + j];
#pragma unroll
        for (int r = 0; r < TI; r++) {
            float4 e4 = *(const float4*)&ei[r][k];
            acc[r] += fabsf(e4.x - vj0) * w4.x + fabsf(e4.y - vj1) * w4.y +
                      fabsf(e4.z - vj2) * w4.z + fabsf(e4.w - vj3) * w4.w;
        }
    }

    float bmv = *bm;
#pragma unroll
    for (int r = 0; r < TI; r++) {
        int i = i0 + r;
        if (j > i) {
            int p = i * (2 * N_ROI - i - 1) / 2 + (j - i - 1);
            out[p] = acc[r] + bmv;
        }
    }
}

// ---------------- launch ----------------
extern "C" void kernel_launch(void* const* d_in, const int* in_sizes, int n_in,
                              void* d_out, int out_size) {
    const float* feat   = (const float*)d_in[0];
    const float* conv_w = (const float*)d_in[2];
    const float* conv_b = (const float*)d_in[3];
    const float* w1     = (const float*)d_in[4];
    const float* b1     = (const float*)d_in[5];
    const float* w2     = (const float*)d_in[6];
    const float* b2     = (const float*)d_in[7];
    const float* wm     = (const float*)d_in[8];
    const float* bm     = (const float*)d_in[9];
    float* out = (float*)d_out;

    const int SMEM = 2 * STAGE_B;
    const int PSMEM = 64 * 201 * 4;          // 51456
    const int F2SMEM = (8192 + 8192 + 8 * 264) * 4;
    static bool attr_set = false;
    if (!attr_set) {
        cudaFuncSetAttribute(gemm_sp<0>, cudaFuncAttributeMaxDynamicSharedMemorySize, SMEM);
        cudaFuncSetAttribute(gemm_sp<1>, cudaFuncAttributeMaxDynamicSharedMemorySize, SMEM);
        cudaFuncSetAttribute(prep_kernel, cudaFuncAttributeMaxDynamicSharedMemorySize, PSMEM);
        cudaFuncSetAttribute(fc2_kernel, cudaFuncAttributeMaxDynamicSharedMemorySize, F2SMEM);
        attr_set = true;
    }

    prep_kernel<<<1024 + 12544 + 2304, 256, PSMEM>>>(feat, conv_w, w1);
    gemm_sp<0><<<dim3(2, MTOT / 128), 256, SMEM>>>(conv_b);
    gemm_sp<1><<<dim3(HID / 128, N_ROI / 128, 4), 256, SMEM>>>(nullptr);
    fc2_kernel<<<N_ROI / 8, 1024, F2SMEM>>>(w2, b1, b2);
    pair_kernel<<<dim3(N_ROI / 256, N_ROI / TI), 256>>>(wm, bm, out);
}

// round 14
// speedup vs baseline: 1.0526x; 1.0526x over previous
#include <cuda_runtime.h>
#include <cuda_fp16.h>
#include <cstdint>

#define N_ROI 1024
#define FLAT  12544
#define HID   1024
#define EMB   256
#define MTOT  50176

// ---------------- scratch ----------------
__device__ __half g_f[(size_t)N_ROI * 196 * 256];    // NHWC fp16 features
__device__ __half g_cw[9 * 256 * 256];               // conv weights [tap][oc][ic]
__device__ __half g_w1[(size_t)HID * FLAT];          // [col][knew]
__device__ __half g_x[(size_t)N_ROI * FLAT];         // conv out fp16 [roi][o*256+oc]
__device__ float g_hp[4 * 1024 * 1024];              // fc1 split-K partials
__device__ float g_e[(size_t)N_ROI * EMB];
__device__ float g_eT[(size_t)EMB * N_ROI];

// ---------------- helpers ----------------
__device__ __forceinline__ uint32_t smem_u32(const void* p) {
    uint32_t a;
    asm("{ .reg .u64 t; cvta.to.shared.u64 t, %1; cvt.u32.u64 %0, t; }" : "=r"(a) : "l"(p));
    return a;
}
__device__ __forceinline__ void ldsm4(uint32_t& r0, uint32_t& r1, uint32_t& r2, uint32_t& r3,
                                      uint32_t addr) {
    asm volatile("ldmatrix.sync.aligned.m8n8.x4.shared.b16 {%0,%1,%2,%3}, [%4];"
                 : "=r"(r0), "=r"(r1), "=r"(r2), "=r"(r3) : "r"(addr));
}
__device__ __forceinline__ void mma16816(float* d, const uint32_t* a, uint32_t b0, uint32_t b1) {
    asm volatile(
        "mma.sync.aligned.m16n8k16.row.col.f32.f16.f16.f32 "
        "{%0,%1,%2,%3},{%4,%5,%6,%7},{%8,%9},{%0,%1,%2,%3};"
        : "+f"(d[0]), "+f"(d[1]), "+f"(d[2]), "+f"(d[3])
        : "r"(a[0]), "r"(a[1]), "r"(a[2]), "r"(a[3]), "r"(b0), "r"(b1));
}
__device__ __forceinline__ void cpa16(uint32_t dst, const void* src) {
    asm volatile("cp.async.ca.shared.global [%0], [%1], 16;" :: "r"(dst), "l"(src));
}
__device__ __forceinline__ void cpa16z(uint32_t dst, const void* src, uint32_t sz) {
    asm volatile("cp.async.ca.shared.global [%0], [%1], 16, %2;"
                 :: "r"(dst), "l"(src), "r"(sz));
}
__device__ __forceinline__ void cpa_commit() {
    asm volatile("cp.async.commit_group;" ::: "memory");
}
template <int N>
__device__ __forceinline__ void cpa_wait() {
    asm volatile("cp.async.wait_group %0;" :: "n"(N) : "memory");
}

// ---------------- fused prep (R11): nhwc | w1 transpose | conv-w convert -----
__global__ __launch_bounds__(256) void prep_kernel(const float* __restrict__ feat,
                                                   const float* __restrict__ conv_w,
                                                   const float* __restrict__ w1) {
    __shared__ float sm[32 * 201];
    int b = blockIdx.x;
    if (b < 1024) {
        int n = b;
        const float* src = feat + (size_t)n * 50176;
        size_t obase = (size_t)n * 50176;
        float (*tile)[201] = (float(*)[201])sm;
        for (int cb = 0; cb < 8; cb++) {
            __syncthreads();
            for (int i = threadIdx.x; i < 6272; i += 256) {
                int c = i / 196, p = i % 196;
                tile[c][p] = src[(cb * 32 + c) * 196 + p];
            }
            __syncthreads();
            int c = threadIdx.x & 31, p0 = threadIdx.x >> 5;
            for (int p = p0; p < 196; p += 8)
                g_f[obase + (size_t)p * 256 + cb * 32 + c] = __float2half(tile[c][p]);
        }
    } else if (b < 1024 + 12544) {
        int idx = b - 1024;
        int knew0 = (idx % 392) * 32, col0 = (idx / 392) * 32;
        float (*t)[33] = (float(*)[33])sm;
        int tr = threadIdx.x >> 5, tc = threadIdx.x & 31;
#pragma unroll
        for (int i = 0; i < 4; i++) {
            int knew = knew0 + tr + i * 8;
            int oc = knew & 255, o = knew >> 8;
            t[tr + i * 8][tc] = w1[(size_t)(oc * 49 + o) * HID + col0 + tc];
        }
        __syncthreads();
#pragma unroll
        for (int i = 0; i < 4; i++) {
            int crow = tr + i * 8;
            g_w1[(size_t)(col0 + crow) * FLAT + knew0 + tc] = __float2half(t[tc][crow]);
        }
    } else {
        int i = (b - 13568) * 256 + threadIdx.x;
        int t = i >> 16, rem = i & 65535;
        int oc = rem >> 8, ic = rem & 255;
        g_cw[i] = __float2half(conv_w[oc * 2304 + ic * 9 + t]);
    }
}

// ---------------- single-pass fp16 HMMA GEMM, BK=64 chunks, 2-stage ----------
#define ROW_B 144
#define TILE_B (128 * ROW_B)
#define STAGE_B (2 * TILE_B)
template <int MODE>
__global__ __launch_bounds__(256, 2) void gemm_sp(const float* __restrict__ bias) {
    constexpr int TOTAL = MODE ? (3136 / 64) : (2304 / 64);
    extern __shared__ __align__(128) char smem[];
    uint32_t sb = smem_u32(smem);

    int tid = threadIdx.x, lane = tid & 31, wid = tid >> 5;
    int wm = wid >> 1, wn = wid & 1;
    int m0 = blockIdx.y * 128, n0 = blockIdx.x * 128;

    int rL = tid >> 2, sL = tid & 3;
    uint32_t dA0 = rL * ROW_B + sL * 16, dA1 = (rL + 64) * ROW_B + sL * 16;

    int ny0 = 0, oy0 = 0, ox0 = 0, ny1 = 0, oy1 = 0, ox1 = 0;
    size_t a0 = 0, a1 = 0, b0 = 0, b1 = 0;
    if (MODE == 0) {
        int rA0 = m0 + rL, rA1 = rA0 + 64;
        ny0 = rA0 / 49; int o0 = rA0 - ny0 * 49; oy0 = o0 / 7; ox0 = o0 - oy0 * 7;
        ny1 = rA1 / 49; int o1 = rA1 - ny1 * 49; oy1 = o1 / 7; ox1 = o1 - oy1 * 7;
    } else {
        size_t koff = (size_t)blockIdx.z * 3136;
        a0 = (size_t)(m0 + rL) * FLAT + koff + sL * 8;
        a1 = (size_t)(m0 + rL + 64) * FLAT + koff + sL * 8;
        b0 = (size_t)(n0 + rL) * FLAT + koff + sL * 8;
        b1 = (size_t)(n0 + rL + 64) * FLAT + koff + sL * 8;
    }

    float acc[2][8][4];
#pragma unroll
    for (int i = 0; i < 2; i++)
#pragma unroll
        for (int j = 0; j < 8; j++)
#pragma unroll
            for (int q = 0; q < 4; q++) acc[i][j][q] = 0.f;

    auto load_stage = [&](int it, int st) {
        uint32_t base = sb + st * STAGE_B;
        if (MODE == 0) {
            int t = it >> 2;
            int ky = t / 3, kx = t - ky * 3;
            int ic0 = ((it & 3) << 6) + sL * 8;
            int iy0 = 2 * oy0 + ky - 1, ix0 = 2 * ox0 + kx - 1;
            int iy1 = 2 * oy1 + ky - 1, ix1 = 2 * ox1 + kx - 1;
            uint32_t v0 = ((unsigned)iy0 < 14u && (unsigned)ix0 < 14u) ? 16u : 0u;
            uint32_t v1 = ((unsigned)iy1 < 14u && (unsigned)ix1 < 14u) ? 16u : 0u;
            size_t s0 = ((size_t)ny0 * 196 + (v0 ? iy0 * 14 + ix0 : 0)) * 256 + ic0;
            size_t s1 = ((size_t)ny1 * 196 + (v1 ? iy1 * 14 + ix1 : 0)) * 256 + ic0;
            size_t bw0 = (size_t)t * 65536 + (size_t)(n0 + rL) * 256 + ic0;
            cpa16z(base + dA0,              g_f + s0, v0);
            cpa16z(base + dA0 + 64,         g_f + s0 + 32, v0);
            cpa16z(base + dA1,              g_f + s1, v1);
            cpa16z(base + dA1 + 64,         g_f + s1 + 32, v1);
            cpa16(base + TILE_B + dA0,      g_cw + bw0);
            cpa16(base + TILE_B + dA0 + 64, g_cw + bw0 + 32);
            cpa16(base + TILE_B + dA1,      g_cw + bw0 + 64 * 256);
            cpa16(base + TILE_B + dA1 + 64, g_cw + bw0 + 64 * 256 + 32);
        } else {
            size_t ko = (size_t)it * 64;
            cpa16(base + dA0,               g_x + a0 + ko);
            cpa16(base + dA0 + 64,          g_x + a0 + ko + 32);
            cpa16(base + dA1,               g_x + a1 + ko);
            cpa16(base + dA1 + 64,          g_x + a1 + ko + 32);
            cpa16(base + TILE_B + dA0,      g_w1 + b0 + ko);
            cpa16(base + TILE_B + dA0 + 64, g_w1 + b0 + ko + 32);
            cpa16(base + TILE_B + dA1,      g_w1 + b1 + ko);
            cpa16(base + TILE_B + dA1 + 64, g_w1 + b1 + ko + 32);
        }
        cpa_commit();
    };

    uint32_t lmo = (lane & 15) * ROW_B + (lane >> 4) * 16;
    uint32_t aOff = wm * 32 * ROW_B + lmo;
    uint32_t bOff = wn * 64 * ROW_B + lmo;

    load_stage(0, 0);
    for (int it = 0; it < TOTAL; it++) {
        cpa_wait<0>();
        __syncthreads();
        if (it + 1 < TOTAL) load_stage(it + 1, (it + 1) & 1);

        uint32_t base = sb + (it & 1) * STAGE_B;
        uint32_t aA = base + aOff, bB = base + TILE_B + bOff;

#pragma unroll
        for (int ks = 0; ks < 4; ks++) {
            uint32_t a[2][4], b[8][2];
#pragma unroll
            for (int mt = 0; mt < 2; mt++)
                ldsm4(a[mt][0], a[mt][1], a[mt][2], a[mt][3],
                      aA + mt * 16 * ROW_B + ks * 32);
#pragma unroll
            for (int q = 0; q < 4; q++) {
                uint32_t r0, r1, r2, r3;
                ldsm4(r0, r1, r2, r3, bB + q * 16 * ROW_B + ks * 32);
                b[2 * q][0] = r0; b[2 * q][1] = r2;
                b[2 * q + 1][0] = r1; b[2 * q + 1][1] = r3;
            }
#pragma unroll
            for (int mt = 0; mt < 2; mt++)
#pragma unroll
                for (int nt = 0; nt < 8; nt++)
                    mma16816(acc[mt][nt], a[mt], b[nt][0], b[nt][1]);
        }
    }
    __syncthreads();

    int rbase = lane >> 2, cbase = (lane & 3) * 2;
#pragma unroll
    for (int mt = 0; mt < 2; mt++) {
#pragma unroll
        for (int nt = 0; nt < 8; nt++) {
            int n = n0 + wn * 64 + nt * 8 + cbase;
            float b0v = 0.f, b1v = 0.f;
            if (MODE == 0) { b0v = bias[n]; b1v = bias[n + 1]; }
#pragma unroll
            for (int half = 0; half < 2; half++) {
                int m = m0 + wm * 32 + mt * 16 + rbase + half * 8;
                if (MODE == 0) {
                    float v0 = fmaxf(acc[mt][nt][half * 2 + 0] + b0v, 0.f);
                    float v1 = fmaxf(acc[mt][nt][half * 2 + 1] + b1v, 0.f);
                    int roi = m / 49, o = m - roi * 49;
                    size_t dst = (size_t)roi * FLAT + o * 256 + n;
                    *(__half2*)&g_x[dst] = __floats2half2_rn(v0, v1);
                } else {
                    float2 v = make_float2(acc[mt][nt][half * 2 + 0],
                                           acc[mt][nt][half * 2 + 1]);
                    *(float2*)&g_hp[(size_t)blockIdx.z * 1048576 + (size_t)m * HID + n] = v;
                }
            }
        }
    }
}

// ---------------- fc2 (fused reduce+bias+relu) + L2-normalize, unroll 16 -----
__global__ __launch_bounds__(1024) void fc2_kernel(const float* __restrict__ w2,
                                                   const float* __restrict__ b1,
                                                   const float* __restrict__ b2) {
    extern __shared__ float dsm[];
    float* hs   = dsm;                       // [8][1024]
    float* part = dsm + 8192;                // [4][8][256]
    float* sred = dsm + 16384;               // [8][264]
    int n0 = blockIdx.x * 8;
    int tid = threadIdx.x, g = tid >> 8, c = tid & 255;

    for (int i = tid; i < 8192; i += 1024) {
        int r = i >> 10, k = i & 1023;
        size_t off = (size_t)(n0 + r) * HID + k;
        float s = g_hp[off] + g_hp[off + 1048576] + g_hp[off + 2097152] +
                  g_hp[off + 3145728] + b1[k];
        hs[r * 1024 + k] = fmaxf(s, 0.f);
    }
    __syncthreads();

    float acc[8];
#pragma unroll
    for (int r = 0; r < 8; r++) acc[r] = 0.f;
    int k0 = g * 256;
#pragma unroll 16
    for (int kk = 0; kk < 256; kk++) {
        float w = w2[(size_t)(k0 + kk) * 256 + c];
#pragma unroll
        for (int r = 0; r < 8; r++)
            acc[r] += hs[r * 1024 + k0 + kk] * w;
    }
#pragma unroll
    for (int r = 0; r < 8; r++)
        part[(g * 8 + r) * 256 + c] = acc[r];
    __syncthreads();

    float val[2];
#pragma unroll
    for (int h = 0; h < 2; h++) {
        int r = g + h * 4;
        val[h] = part[(0 * 8 + r) * 256 + c] + part[(1 * 8 + r) * 256 + c] +
                 part[(2 * 8 + r) * 256 + c] + part[(3 * 8 + r) * 256 + c] + b2[c];
        sred[r * 264 + c] = val[h] * val[h];
    }
    __syncthreads();
    for (int s = 128; s > 0; s >>= 1) {
        if (c < s) {
            sred[g * 264 + c] += sred[g * 264 + c + s];
            sred[(g + 4) * 264 + c] += sred[(g + 4) * 264 + c + s];
        }
        __syncthreads();
    }
#pragma unroll
    for (int h = 0; h < 2; h++) {
        int r = g + h * 4;
        float v = val[h] / sqrtf(sred[r * 264]);
        g_e[(size_t)(n0 + r) * EMB + c] = v;
        g_eT[(size_t)c * N_ROI + (n0 + r)] = v;
    }
}

// ---------------- pairwise, float4 k (R12) ----------------
#define TI 16
__global__ __launch_bounds__(256) void pair_kernel(const float* __restrict__ wm,
                                                   const float* __restrict__ bm,
                                                   float* __restrict__ out) {
    int i0 = blockIdx.y * TI;
    int j0 = blockIdx.x * 256;
    if (j0 + 255 <= i0) return;

    __shared__ float ei[TI][256];
    __shared__ float wms[256];
    int tid = threadIdx.x;
    wms[tid] = wm[tid];
#pragma unroll
    for (int r = 0; r < TI; r++)
        ei[r][tid] = g_e[(size_t)(i0 + r) * EMB + tid];
    __syncthreads();

    int j = j0 + tid;
    float acc[TI];
#pragma unroll
    for (int r = 0; r < TI; r++) acc[r] = 0.f;

#pragma unroll 2
    for (int k = 0; k < 256; k += 4) {
        float4 w4 = *(const float4*)&wms[k];
        float vj0 = g_eT[(size_t)k * N_ROI + j];
        float vj1 = g_eT[(size_t)(k + 1) * N_ROI + j];
        float vj2 = g_eT[(size_t)(k + 2) * N_ROI + j];
        float vj3 = g_eT[(size_t)(k + 3) * N_ROI + j];
#pragma unroll
        for (int r = 0; r < TI; r++) {
            float4 e4 = *(const float4*)&ei[r][k];
            acc[r] += fabsf(e4.x - vj0) * w4.x + fabsf(e4.y - vj1) * w4.y +
                      fabsf(e4.z - vj2) * w4.z + fabsf(e4.w - vj3) * w4.w;
        }
    }

    float bmv = *bm;
#pragma unroll
    for (int r = 0; r < TI; r++) {
        int i = i0 + r;
        if (j > i) {
            int p = i * (2 * N_ROI - i - 1) / 2 + (j - i - 1);
            out[p] = acc[r] + bmv;
        }
    }
}

// ---------------- launch ----------------
extern "C" void kernel_launch(void* const* d_in, const int* in_sizes, int n_in,
                              void* d_out, int out_size) {
    const float* feat   = (const float*)d_in[0];
    const float* conv_w = (const float*)d_in[2];
    const float* conv_b = (const float*)d_in[3];
    const float* w1     = (const float*)d_in[4];
    const float* b1     = (const float*)d_in[5];
    const float* w2     = (const float*)d_in[6];
    const float* b2     = (const float*)d_in[7];
    const float* wm     = (const float*)d_in[8];
    const float* bm     = (const float*)d_in[9];
    float* out = (float*)d_out;

    const int SMEM = 2 * STAGE_B;
    const int F2SMEM = (8192 + 8192 + 8 * 264) * 4;
    static bool attr_set = false;
    if (!attr_set) {
        cudaFuncSetAttribute(gemm_sp<0>, cudaFuncAttributeMaxDynamicSharedMemorySize, SMEM);
        cudaFuncSetAttribute(gemm_sp<1>, cudaFuncAttributeMaxDynamicSharedMemorySize, SMEM);
        cudaFuncSetAttribute(fc2_kernel, cudaFuncAttributeMaxDynamicSharedMemorySize, F2SMEM);
        attr_set = true;
    }

    prep_kernel<<<1024 + 12544 + 2304, 256>>>(feat, conv_w, w1);
    gemm_sp<0><<<dim3(2, MTOT / 128), 256, SMEM>>>(conv_b);
    gemm_sp<1><<<dim3(HID / 128, N_ROI / 128, 4), 256, SMEM>>>(nullptr);
    fc2_kernel<<<N_ROI / 8, 1024, F2SMEM>>>(w2, b1, b2);
    pair_kernel<<<dim3(N_ROI / 256, N_ROI / TI), 256>>>(wm, bm, out);
}

// round 15
// speedup vs baseline: 1.1189x; 1.0630x over previous
#include <cuda_runtime.h>
#include <cuda_fp16.h>
#include <cstdint>

#define N_ROI 1024
#define FLAT  12544
#define HID   1024
#define EMB   256
#define MTOT  50176

// ---------------- scratch ----------------
__device__ __half g_f[(size_t)N_ROI * 196 * 256];    // NHWC fp16 features
__device__ __half g_cw[9 * 256 * 256];               // conv weights [tap][oc][ic]
__device__ __half g_w1[(size_t)HID * FLAT];          // [col][knew]
__device__ __half g_w2t[256 * 1024];                 // w2 transposed [c][k] fp16
__device__ __half g_x[(size_t)N_ROI * FLAT];         // conv out fp16 [roi][o*256+oc]
__device__ __half g_h2[(size_t)N_ROI * HID];         // fc1 out fp16
__device__ float g_hp[4 * 1024 * 1024];              // split-K partials (fc1 then fc2)
__device__ float g_e[(size_t)N_ROI * EMB];
__device__ float g_eT[(size_t)EMB * N_ROI];

// ---------------- helpers ----------------
__device__ __forceinline__ uint32_t smem_u32(const void* p) {
    uint32_t a;
    asm("{ .reg .u64 t; cvta.to.shared.u64 t, %1; cvt.u32.u64 %0, t; }" : "=r"(a) : "l"(p));
    return a;
}
__device__ __forceinline__ void ldsm4(uint32_t& r0, uint32_t& r1, uint32_t& r2, uint32_t& r3,
                                      uint32_t addr) {
    asm volatile("ldmatrix.sync.aligned.m8n8.x4.shared.b16 {%0,%1,%2,%3}, [%4];"
                 : "=r"(r0), "=r"(r1), "=r"(r2), "=r"(r3) : "r"(addr));
}
__device__ __forceinline__ void mma16816(float* d, const uint32_t* a, uint32_t b0, uint32_t b1) {
    asm volatile(
        "mma.sync.aligned.m16n8k16.row.col.f32.f16.f16.f32 "
        "{%0,%1,%2,%3},{%4,%5,%6,%7},{%8,%9},{%0,%1,%2,%3};"
        : "+f"(d[0]), "+f"(d[1]), "+f"(d[2]), "+f"(d[3])
        : "r"(a[0]), "r"(a[1]), "r"(a[2]), "r"(a[3]), "r"(b0), "r"(b1));
}
__device__ __forceinline__ void cpa16(uint32_t dst, const void* src) {
    asm volatile("cp.async.ca.shared.global [%0], [%1], 16;" :: "r"(dst), "l"(src));
}
__device__ __forceinline__ void cpa16z(uint32_t dst, const void* src, uint32_t sz) {
    asm volatile("cp.async.ca.shared.global [%0], [%1], 16, %2;"
                 :: "r"(dst), "l"(src), "r"(sz));
}
__device__ __forceinline__ void cpa_commit() {
    asm volatile("cp.async.commit_group;" ::: "memory");
}
template <int N>
__device__ __forceinline__ void cpa_wait() {
    asm volatile("cp.async.wait_group %0;" :: "n"(N) : "memory");
}

// ---------------- fused prep: nhwc | w1 transpose | conv-w | w2 transpose ----
// blocks [0,1024): nhwc   [1024,13568): w1   [13568,15872): conv-w
// [15872,16128): w2 transpose (1024x256 -> [c][k])
__global__ __launch_bounds__(256) void prep_kernel(const float* __restrict__ feat,
                                                   const float* __restrict__ conv_w,
                                                   const float* __restrict__ w1,
                                                   const float* __restrict__ w2) {
    __shared__ float sm[32 * 201];
    int b = blockIdx.x;
    if (b < 1024) {
        int n = b;
        const float* src = feat + (size_t)n * 50176;
        size_t obase = (size_t)n * 50176;
        float (*tile)[201] = (float(*)[201])sm;
        for (int cb = 0; cb < 8; cb++) {
            __syncthreads();
            for (int i = threadIdx.x; i < 6272; i += 256) {
                int c = i / 196, p = i % 196;
                tile[c][p] = src[(cb * 32 + c) * 196 + p];
            }
            __syncthreads();
            int c = threadIdx.x & 31, p0 = threadIdx.x >> 5;
            for (int p = p0; p < 196; p += 8)
                g_f[obase + (size_t)p * 256 + cb * 32 + c] = __float2half(tile[c][p]);
        }
    } else if (b < 1024 + 12544) {
        int idx = b - 1024;
        int knew0 = (idx % 392) * 32, col0 = (idx / 392) * 32;
        float (*t)[33] = (float(*)[33])sm;
        int tr = threadIdx.x >> 5, tc = threadIdx.x & 31;
#pragma unroll
        for (int i = 0; i < 4; i++) {
            int knew = knew0 + tr + i * 8;
            int oc = knew & 255, o = knew >> 8;
            t[tr + i * 8][tc] = w1[(size_t)(oc * 49 + o) * HID + col0 + tc];
        }
        __syncthreads();
#pragma unroll
        for (int i = 0; i < 4; i++) {
            int crow = tr + i * 8;
            g_w1[(size_t)(col0 + crow) * FLAT + knew0 + tc] = __float2half(t[tc][crow]);
        }
    } else if (b < 15872) {
        int i = (b - 13568) * 256 + threadIdx.x;
        int t = i >> 16, rem = i & 65535;
        int oc = rem >> 8, ic = rem & 255;
        g_cw[i] = __float2half(conv_w[oc * 2304 + ic * 9 + t]);
    } else {
        int idx = b - 15872;                         // 256 tiles: 32 k-tiles x 8 c-tiles
        int k0 = (idx & 31) * 32, c0 = (idx >> 5) * 32;
        float (*t)[33] = (float(*)[33])sm;
        int tr = threadIdx.x >> 5, tc = threadIdx.x & 31;
#pragma unroll
        for (int i = 0; i < 4; i++)
            t[tr + i * 8][tc] = w2[(size_t)(k0 + tr + i * 8) * 256 + c0 + tc];
        __syncthreads();
#pragma unroll
        for (int i = 0; i < 4; i++) {
            int crow = tr + i * 8;
            g_w2t[(size_t)(c0 + crow) * 1024 + k0 + tc] = __float2half(t[tc][crow]);
        }
    }
}

// ---------------- single-pass fp16 HMMA GEMM, BK=64 chunks, 2-stage ----------
// MODE 0: conv (A gathered NHWC, B=g_cw; epi -> g_x fp16, bias+relu)
// MODE 1: fc1  (A=g_x, B=g_w1, K=12544 split 4; partials -> g_hp)
// MODE 2: fc2  (A=g_h2, B=g_w2t, K=1024 split 8; partials -> g_hp)
#define ROW_B 144
#define TILE_B (128 * ROW_B)
#define STAGE_B (2 * TILE_B)
template <int MODE>
__global__ __launch_bounds__(256, 2) void gemm_sp(const float* __restrict__ bias) {
    constexpr int TOTAL = MODE == 0 ? 36 : (MODE == 1 ? 49 : 2);
    constexpr int KSTR  = MODE == 1 ? FLAT : 1024;   // A/B row stride (linear modes)
    constexpr int KOFF  = MODE == 1 ? 3136 : 128;    // K per split
    extern __shared__ __align__(128) char smem[];
    uint32_t sb = smem_u32(smem);

    int tid = threadIdx.x, lane = tid & 31, wid = tid >> 5;
    int wm = wid >> 1, wn = wid & 1;
    int m0 = blockIdx.y * 128, n0 = blockIdx.x * 128;

    int rL = tid >> 2, sL = tid & 3;
    uint32_t dA0 = rL * ROW_B + sL * 16, dA1 = (rL + 64) * ROW_B + sL * 16;

    int ny0 = 0, oy0 = 0, ox0 = 0, ny1 = 0, oy1 = 0, ox1 = 0;
    size_t a0 = 0, a1 = 0, b0 = 0, b1 = 0;
    if (MODE == 0) {
        int rA0 = m0 + rL, rA1 = rA0 + 64;
        ny0 = rA0 / 49; int o0 = rA0 - ny0 * 49; oy0 = o0 / 7; ox0 = o0 - oy0 * 7;
        ny1 = rA1 / 49; int o1 = rA1 - ny1 * 49; oy1 = o1 / 7; ox1 = o1 - oy1 * 7;
    } else {
        size_t koff = (size_t)blockIdx.z * KOFF;
        a0 = (size_t)(m0 + rL) * KSTR + koff + sL * 8;
        a1 = (size_t)(m0 + rL + 64) * KSTR + koff + sL * 8;
        b0 = (size_t)(n0 + rL) * KSTR + koff + sL * 8;
        b1 = (size_t)(n0 + rL + 64) * KSTR + koff + sL * 8;
    }

    float acc[2][8][4];
#pragma unroll
    for (int i = 0; i < 2; i++)
#pragma unroll
        for (int j = 0; j < 8; j++)
#pragma unroll
            for (int q = 0; q < 4; q++) acc[i][j][q] = 0.f;

    auto load_stage = [&](int it, int st) {
        uint32_t base = sb + st * STAGE_B;
        if (MODE == 0) {
            int t = it >> 2;
            int ky = t / 3, kx = t - ky * 3;
            int ic0 = ((it & 3) << 6) + sL * 8;
            int iy0 = 2 * oy0 + ky - 1, ix0 = 2 * ox0 + kx - 1;
            int iy1 = 2 * oy1 + ky - 1, ix1 = 2 * ox1 + kx - 1;
            uint32_t v0 = ((unsigned)iy0 < 14u && (unsigned)ix0 < 14u) ? 16u : 0u;
            uint32_t v1 = ((unsigned)iy1 < 14u && (unsigned)ix1 < 14u) ? 16u : 0u;
            size_t s0 = ((size_t)ny0 * 196 + (v0 ? iy0 * 14 + ix0 : 0)) * 256 + ic0;
            size_t s1 = ((size_t)ny1 * 196 + (v1 ? iy1 * 14 + ix1 : 0)) * 256 + ic0;
            size_t bw0 = (size_t)t * 65536 + (size_t)(n0 + rL) * 256 + ic0;
            cpa16z(base + dA0,              g_f + s0, v0);
            cpa16z(base + dA0 + 64,         g_f + s0 + 32, v0);
            cpa16z(base + dA1,              g_f + s1, v1);
            cpa16z(base + dA1 + 64,         g_f + s1 + 32, v1);
            cpa16(base + TILE_B + dA0,      g_cw + bw0);
            cpa16(base + TILE_B + dA0 + 64, g_cw + bw0 + 32);
            cpa16(base + TILE_B + dA1,      g_cw + bw0 + 64 * 256);
            cpa16(base + TILE_B + dA1 + 64, g_cw + bw0 + 64 * 256 + 32);
        } else {
            const __half* A = MODE == 1 ? g_x : g_h2;
            const __half* B = MODE == 1 ? g_w1 : g_w2t;
            size_t ko = (size_t)it * 64;
            cpa16(base + dA0,               A + a0 + ko);
            cpa16(base + dA0 + 64,          A + a0 + ko + 32);
            cpa16(base + dA1,               A + a1 + ko);
            cpa16(base + dA1 + 64,          A + a1 + ko + 32);
            cpa16(base + TILE_B + dA0,      B + b0 + ko);
            cpa16(base + TILE_B + dA0 + 64, B + b0 + ko + 32);
            cpa16(base + TILE_B + dA1,      B + b1 + ko);
            cpa16(base + TILE_B + dA1 + 64, B + b1 + ko + 32);
        }
        cpa_commit();
    };

    uint32_t lmo = (lane & 15) * ROW_B + (lane >> 4) * 16;
    uint32_t aOff = wm * 32 * ROW_B + lmo;
    uint32_t bOff = wn * 64 * ROW_B + lmo;

    load_stage(0, 0);
    for (int it = 0; it < TOTAL; it++) {
        cpa_wait<0>();
        __syncthreads();
        if (it + 1 < TOTAL) load_stage(it + 1, (it + 1) & 1);

        uint32_t base = sb + (it & 1) * STAGE_B;
        uint32_t aA = base + aOff, bB = base + TILE_B + bOff;

#pragma unroll
        for (int ks = 0; ks < 4; ks++) {
            uint32_t a[2][4], b[8][2];
#pragma unroll
            for (int mt = 0; mt < 2; mt++)
                ldsm4(a[mt][0], a[mt][1], a[mt][2], a[mt][3],
                      aA + mt * 16 * ROW_B + ks * 32);
#pragma unroll
            for (int q = 0; q < 4; q++) {
                uint32_t r0, r1, r2, r3;
                ldsm4(r0, r1, r2, r3, bB + q * 16 * ROW_B + ks * 32);
                b[2 * q][0] = r0; b[2 * q][1] = r2;
                b[2 * q + 1][0] = r1; b[2 * q + 1][1] = r3;
            }
#pragma unroll
            for (int mt = 0; mt < 2; mt++)
#pragma unroll
                for (int nt = 0; nt < 8; nt++)
                    mma16816(acc[mt][nt], a[mt], b[nt][0], b[nt][1]);
        }
    }
    __syncthreads();

    int rbase = lane >> 2, cbase = (lane & 3) * 2;
#pragma unroll
    for (int mt = 0; mt < 2; mt++) {
#pragma unroll
        for (int nt = 0; nt < 8; nt++) {
            int n = n0 + wn * 64 + nt * 8 + cbase;
            float b0v = 0.f, b1v = 0.f;
            if (MODE == 0) { b0v = bias[n]; b1v = bias[n + 1]; }
#pragma unroll
            for (int half = 0; half < 2; half++) {
                int m = m0 + wm * 32 + mt * 16 + rbase + half * 8;
                if (MODE == 0) {
                    float v0 = fmaxf(acc[mt][nt][half * 2 + 0] + b0v, 0.f);
                    float v1 = fmaxf(acc[mt][nt][half * 2 + 1] + b1v, 0.f);
                    int roi = m / 49, o = m - roi * 49;
                    size_t dst = (size_t)roi * FLAT + o * 256 + n;
                    *(__half2*)&g_x[dst] = __floats2half2_rn(v0, v1);
                } else {
                    float2 v = make_float2(acc[mt][nt][half * 2 + 0],
                                           acc[mt][nt][half * 2 + 1]);
                    size_t dst = MODE == 1
                        ? (size_t)blockIdx.z * 1048576 + (size_t)m * HID + n
                        : (size_t)blockIdx.z * 262144 + (size_t)m * 256 + n;
                    *(float2*)&g_hp[dst] = v;
                }
            }
        }
    }
}

// ---------------- fc1 split-K reduce + bias + relu -> fp16 h ----------------
__global__ void fc1_reduce(const float* __restrict__ b1) {
    int i = blockIdx.x * 256 + threadIdx.x;          // 262144 groups of 4
    const float4* p = (const float4*)g_hp;
    float4 a = p[i], b = p[i + 262144], c = p[i + 524288], d = p[i + 786432];
    int n = (i & 255) * 4;
    float4 bb = *(const float4*)(b1 + n);
    float r0 = fmaxf(a.x + b.x + c.x + d.x + bb.x, 0.f);
    float r1 = fmaxf(a.y + b.y + c.y + d.y + bb.y, 0.f);
    float r2 = fmaxf(a.z + b.z + c.z + d.z + bb.z, 0.f);
    float r3 = fmaxf(a.w + b.w + c.w + d.w + bb.w, 0.f);
    __half2 h01 = __floats2half2_rn(r0, r1);
    __half2 h23 = __floats2half2_rn(r2, r3);
    uint2 u = make_uint2(*(uint32_t*)&h01, *(uint32_t*)&h23);
    *(uint2*)&g_h2[(size_t)i * 4] = u;
}

// ---------------- fc2 split-K reduce + bias + L2-normalize ----------------
__global__ __launch_bounds__(256) void norm_kernel(const float* __restrict__ b2) {
    __shared__ float sred[256];
    int row = blockIdx.x;
    int c = threadIdx.x;
    float v = b2[c];
#pragma unroll
    for (int z = 0; z < 8; z++)
        v += g_hp[(size_t)z * 262144 + (size_t)row * 256 + c];
    sred[c] = v * v;
    __syncthreads();
    for (int s = 128; s > 0; s >>= 1) {
        if (c < s) sred[c] += sred[c + s];
        __syncthreads();
    }
    float e = v / sqrtf(sred[0]);
    g_e[(size_t)row * 256 + c] = e;
    g_eT[(size_t)c * N_ROI + row] = e;
}

// ---------------- pairwise (R11 scalar) ----------------
#define TI 16
__global__ __launch_bounds__(256) void pair_kernel(const float* __restrict__ wm,
                                                   const float* __restrict__ bm,
                                                   float* __restrict__ out) {
    int i0 = blockIdx.y * TI;
    int j0 = blockIdx.x * 256;
    if (j0 + 255 <= i0) return;

    __shared__ float ei[TI][256];
    __shared__ float wms[256];
    int tid = threadIdx.x;
    wms[tid] = wm[tid];
#pragma unroll
    for (int r = 0; r < TI; r++)
        ei[r][tid] = g_e[(size_t)(i0 + r) * EMB + tid];
    __syncthreads();

    int j = j0 + tid;
    float acc[TI];
#pragma unroll
    for (int r = 0; r < TI; r++) acc[r] = 0.f;

#pragma unroll 4
    for (int k = 0; k < 256; k++) {
        float vj = g_eT[(size_t)k * N_ROI + j];
        float wk = wms[k];
#pragma unroll
        for (int r = 0; r < TI; r++)
            acc[r] += fabsf(ei[r][k] - vj) * wk;
    }

    float bmv = *bm;
#pragma unroll
    for (int r = 0; r < TI; r++) {
        int i = i0 + r;
        if (j > i) {
            int p = i * (2 * N_ROI - i - 1) / 2 + (j - i - 1);
            out[p] = acc[r] + bmv;
        }
    }
}

// ---------------- launch ----------------
extern "C" void kernel_launch(void* const* d_in, const int* in_sizes, int n_in,
                              void* d_out, int out_size) {
    const float* feat   = (const float*)d_in[0];
    const float* conv_w = (const float*)d_in[2];
    const float* conv_b = (const float*)d_in[3];
    const float* w1     = (const float*)d_in[4];
    const float* b1     = (const float*)d_in[5];
    const float* w2     = (const float*)d_in[6];
    const float* b2     = (const float*)d_in[7];
    const float* wm     = (const float*)d_in[8];
    const float* bm     = (const float*)d_in[9];
    float* out = (float*)d_out;

    const int SMEM = 2 * STAGE_B;
    static bool attr_set = false;
    if (!attr_set) {
        cudaFuncSetAttribute(gemm_sp<0>, cudaFuncAttributeMaxDynamicSharedMemorySize, SMEM);
        cudaFuncSetAttribute(gemm_sp<1>, cudaFuncAttributeMaxDynamicSharedMemorySize, SMEM);
        cudaFuncSetAttribute(gemm_sp<2>, cudaFuncAttributeMaxDynamicSharedMemorySize, SMEM);
        attr_set = true;
    }

    prep_kernel<<<1024 + 12544 + 2304 + 256, 256>>>(feat, conv_w, w1, w2);
    gemm_sp<0><<<dim3(2, MTOT / 128), 256, SMEM>>>(conv_b);
    gemm_sp<1><<<dim3(HID / 128, N_ROI / 128, 4), 256, SMEM>>>(nullptr);
    fc1_reduce<<<1024, 256>>>(b1);
    gemm_sp<2><<<dim3(EMB / 128, N_ROI / 128, 8), 256, SMEM>>>(nullptr);
    norm_kernel<<<N_ROI, 256>>>(b2);
    pair_kernel<<<dim3(N_ROI / 256, N_ROI / TI), 256>>>(wm, bm, out);
}